// round 16
// baseline (speedup 1.0000x reference)
#include <cuda_runtime.h>

#define TT  128
#define BSZ 64
#define DD  1024
#define HH  1024
#define NG  4096   // 4*H

typedef unsigned int u32;
typedef unsigned long long u64;

// Scratch (device globals: no allocation allowed in kernel_launch)
__device__ __align__(16) float g_G[(size_t)TT * BSZ * NG];     // x@Wx + b
__device__ __align__(16) float g_c[BSZ * HH];                  // cell state
__device__ __align__(16) float g_WhP[(size_t)128 * HH * 32];   // gathered Wh slices
__device__ __align__(16) float g_hT[HH * BSZ];                 // h transposed [hcol][row]

__device__ __forceinline__ u64 fma2(u64 a, u64 b, u64 c) {
    u64 d;
    asm("fma.rn.f32x2 %0, %1, %2, %3;" : "=l"(d) : "l"(a), "l"(b), "l"(c));
    return d;
}
__device__ __forceinline__ u64 pack2(float lo, float hi) {
    u64 d;
    asm("mov.b64 %0, {%1, %2};" : "=l"(d) : "f"(lo), "f"(hi));
    return d;
}
__device__ __forceinline__ void unpack2(u64 v, float& lo, float& hi) {
    asm("mov.b64 {%0, %1}, %2;" : "=f"(lo), "=f"(hi) : "l"(v));
}

// ---------------------------------------------------------------------------
// Phase 0: gather Wh into per-CTA contiguous slices (proven, rounds 11/12).
// ---------------------------------------------------------------------------
__global__ __launch_bounds__(256) void wgather(const float* __restrict__ Wh) {
    const int c  = blockIdx.x;
    const int kb = blockIdx.y;
    const int t  = threadIdx.x;
    float* dst = g_WhP + (size_t)c * (HH * 32);
    #pragma unroll
    for (int i = 0; i < 4; ++i) {
        const int q    = kb * 1024 + i * 256 + t;
        const int base = q * 4;
        const int k    = base >> 5;
        const int j    = base & 31;
        const int gcol = (j >> 3) * HH + c * 8 + (j & 7);
        float4 v = *(const float4*)(Wh + (size_t)k * NG + gcol);
        *(float4*)(dst + base) = v;
    }
}

// ---------------------------------------------------------------------------
// Phase 1: G[8192,4096] = X @ Wx + b — round-1 FFMA kernel VERBATIM
// (plain stores; the round-15 __stcs variant cost ~120us).
// ---------------------------------------------------------------------------
__global__ __launch_bounds__(256) void gemm_pre(const float* __restrict__ X,
                                                const float* __restrict__ Wx,
                                                const float* __restrict__ bias) {
    const int N = NG, K = DD;
    __shared__ float As[2][8][128];
    __shared__ float Bs[2][8][128];

    const int tid  = threadIdx.x;
    const int bx   = blockIdx.x;
    const int by   = blockIdx.y;
    const int aRow = tid >> 1;
    const int aK4  = (tid & 1) << 2;
    const int bK   = tid >> 5;
    const int bN4  = (tid & 31) << 2;
    const int tx   = tid & 15;
    const int ty   = tid >> 4;

    const float* Ap = X  + (size_t)(by * 128) * K;
    const float* Bp = Wx + (size_t)(bx * 128);

    float4 aR = *(const float4*)(Ap + (size_t)aRow * K + aK4);
    float4 bR = *(const float4*)(Bp + (size_t)bK * N + bN4);
    As[0][aK4 + 0][aRow] = aR.x;
    As[0][aK4 + 1][aRow] = aR.y;
    As[0][aK4 + 2][aRow] = aR.z;
    As[0][aK4 + 3][aRow] = aR.w;
    *(float4*)&Bs[0][bK][bN4] = bR;
    __syncthreads();

    u64 acc[4][8];
    #pragma unroll
    for (int i = 0; i < 4; ++i)
        #pragma unroll
        for (int j = 0; j < 8; ++j) acc[i][j] = 0ull;

    const int nT = K / 8;
    for (int tk = 0; tk < nT; ++tk) {
        const int cur = tk & 1;
        if (tk + 1 < nT) {
            const int k0 = (tk + 1) * 8;
            aR = *(const float4*)(Ap + (size_t)aRow * K + k0 + aK4);
            bR = *(const float4*)(Bp + (size_t)(k0 + bK) * N + bN4);
        }
        #pragma unroll
        for (int kk = 0; kk < 8; ++kk) {
            const ulonglong2 a01 = *(const ulonglong2*)&As[cur][kk][ty * 8];
            const ulonglong2 a23 = *(const ulonglong2*)&As[cur][kk][ty * 8 + 4];
            u64 ap[4];
            ap[0] = a01.x; ap[1] = a01.y; ap[2] = a23.x; ap[3] = a23.y;
            float br[8];
            *(float4*)&br[0] = *(const float4*)&Bs[cur][kk][tx * 8];
            *(float4*)&br[4] = *(const float4*)&Bs[cur][kk][tx * 8 + 4];
            #pragma unroll
            for (int j = 0; j < 8; ++j) {
                const u64 bb = pack2(br[j], br[j]);
                #pragma unroll
                for (int i = 0; i < 4; ++i)
                    acc[i][j] = fma2(ap[i], bb, acc[i][j]);
            }
        }
        if (tk + 1 < nT) {
            const int nxt = cur ^ 1;
            As[nxt][aK4 + 0][aRow] = aR.x;
            As[nxt][aK4 + 1][aRow] = aR.y;
            As[nxt][aK4 + 2][aRow] = aR.z;
            As[nxt][aK4 + 3][aRow] = aR.w;
            *(float4*)&Bs[nxt][bK][bN4] = bR;
            __syncthreads();
        }
    }

    float* Gp = g_G + (size_t)(by * 128) * N + (size_t)(bx * 128);
    #pragma unroll
    for (int i = 0; i < 4; ++i) {
        #pragma unroll
        for (int j = 0; j < 8; ++j) {
            float lo, hi;
            unpack2(acc[i][j], lo, hi);
            const int col = tx * 8 + j;
            const float bv = bias[bx * 128 + col];
            Gp[(size_t)(ty * 8 + 2 * i)     * N + col] = lo + bv;
            Gp[(size_t)(ty * 8 + 2 * i + 1) * N + col] = hi + bv;
        }
    }
}

// ---------------------------------------------------------------------------
// Phase 2: warp-autonomous, 16 warps, PRIVATE per-warp duplicated-w smem,
// pack2-free inner loop (round-13-proven layout: slot = m*8 + cg*2 + b,
// row stride 34 u64 -> inner w LDS.128 conflict-free). CK=8, 16 chunks.
// Per kk: 1 h-LDS.128 + 4 w-LDS.128 + 16 fma2 (21 instr, LDS->FMA direct).
// Tail (G/c) prefetched at entry (round-15 proven). __syncwarp only.
// smem: ps [8][64][33] f32 @0           (67584 B)
//       hT [16 w][2][8][32] f32 @67584  (32768 B)
//       wD [16 w][2][8][34] u64 @100352 (69632 B)
//       hs [8][65] f32 @169984          (2080 B)   total 172064 B
// ---------------------------------------------------------------------------
#define STEP_THREADS 512
#define PS9_OFF 0
#define HT9_OFF 67584
#define WD9_OFF 100352
#define HS9_OFF 169984
#define SM9_TOTAL 172064

__global__ __launch_bounds__(STEP_THREADS) void lstm_step9(
    float* __restrict__ out, int t)
{
    extern __shared__ char sm[];
    float* ps = (float*)(sm + PS9_OFF);
    float* hs = (float*)(sm + HS9_OFF);

    const int tid  = threadIdx.x;
    const int cta  = blockIdx.x;         // 0..127
    const int w    = tid >> 5;           // warp 0..15
    const int kg   = w >> 1;             // k-group 0..7
    const int half = w & 1;              // row half
    const int lane = tid & 31;
    const int rg   = lane & 7;
    const int cg   = lane >> 3;
    const int r0   = rg * 4;             // local row (within 32-row half)
    const int j0   = cg * 8;

    // ---- Epilogue prefetch (independent; latency hidden under mainloop) ----
    const int erow  = tid >> 3;
    const int ehl   = tid & 7;
    const int encol = cta * 8 + ehl;
    const float* Grow = g_G + (size_t)t * BSZ * NG + (size_t)erow * NG;
    float gi = __ldcs(Grow + encol);
    float gf = __ldcs(Grow + HH + encol);
    float gg = __ldcs(Grow + 2 * HH + encol);
    float go = __ldcs(Grow + 3 * HH + encol);
    float cold = 0.0f;
    if (t > 0) cold = g_c[erow * HH + encol];

    u64 acc[2][8];
    #pragma unroll
    for (int p = 0; p < 2; ++p)
        #pragma unroll
        for (int j = 0; j < 8; ++j) acc[p][j] = 0ull;

    if (t > 0) {
        const int kbase = kg * 128;
        float* hTw = (float*)(sm + HT9_OFF) + w * 512;        // 2 bufs x 256 f32
        u64*   wDw = (u64*)(sm + WD9_OFF) + w * 544;          // 2 bufs x 272 u64

        const float* wSrc = g_WhP + (size_t)cta * (HH * 32) + (size_t)kbase * 32;

        float4 hv[2], wv[2];
#define P9L(ck) do {                                                          \
    _Pragma("unroll")                                                         \
    for (int i = 0; i < 2; ++i) {                                             \
        const int f  = lane + 32 * i;                                         \
        const int kk = f >> 3, q = f & 7;                                     \
        hv[i] = *(const float4*)(g_hT + (size_t)(kbase + (ck) * 8 + kk) * 64  \
                                 + half * 32 + q * 4);                        \
        wv[i] = *(const float4*)(wSrc + (ck) * 256 + f * 4);                  \
    }                                                                         \
} while (0)
#define P9S(buf) do {                                                         \
    float* hd_ = hTw + (buf) * 256;                                           \
    u64*   wd0 = wDw + (buf) * 272;                                           \
    _Pragma("unroll")                                                         \
    for (int i = 0; i < 2; ++i) {                                             \
        const int f  = lane + 32 * i;                                         \
        const int kk = f >> 3, q = f & 7;                                     \
        *(float4*)(hd_ + kk * 32 + q * 4) = hv[i];                            \
        /* natural cols q*4..q*4+3 -> permuted slots (m*8 + cg2*2 + b) */     \
        u64* wd_ = wd0 + kk * 34 + (q & 1) * 16 + (q >> 1) * 2;               \
        ulonglong2 v0, v1;                                                    \
        v0.x = pack2(wv[i].x, wv[i].x); v0.y = pack2(wv[i].y, wv[i].y);       \
        v1.x = pack2(wv[i].z, wv[i].z); v1.y = pack2(wv[i].w, wv[i].w);       \
        *(ulonglong2*)(wd_)     = v0;                                         \
        *(ulonglong2*)(wd_ + 8) = v1;                                         \
    }                                                                         \
} while (0)

        P9L(0);
        P9S(0);
        __syncwarp();

        for (int c = 0; c < 16; ++c) {
            const int buf = c & 1;
            if (c + 1 < 16) P9L(c + 1);

            const float* hb = hTw + buf * 256;
            const u64*   wb = wDw + buf * 272;
            #pragma unroll
            for (int kk = 0; kk < 8; ++kk) {
                const ulonglong2 hA = *(const ulonglong2*)(hb + kk * 32 + r0);
                #pragma unroll
                for (int m = 0; m < 4; ++m) {
                    const ulonglong2 wd =
                        *(const ulonglong2*)(wb + kk * 34 + m * 8 + cg * 2);
                    acc[0][m * 2]     = fma2(hA.x, wd.x, acc[0][m * 2]);
                    acc[0][m * 2 + 1] = fma2(hA.x, wd.y, acc[0][m * 2 + 1]);
                    acc[1][m * 2]     = fma2(hA.y, wd.x, acc[1][m * 2]);
                    acc[1][m * 2 + 1] = fma2(hA.y, wd.y, acc[1][m * 2 + 1]);
                }
            }
            if (c + 1 < 16) {
                P9S(buf ^ 1);
                __syncwarp();
            }
        }

        // stash partials: ps[kg][half*32 + local_row][col], pad 33
        #pragma unroll
        for (int p = 0; p < 2; ++p) {
            #pragma unroll
            for (int j = 0; j < 8; ++j) {
                float lo, hi;
                unpack2(acc[p][j], lo, hi);
                const int rb = kg * 64 + half * 32 + r0 + 2 * p;
                ps[rb * 33 + j0 + j]       = lo;
                ps[(rb + 1) * 33 + j0 + j] = hi;
            }
        }
    }
    __syncthreads();

    // Epilogue: 512 threads -> 512 outputs; G/c already in registers.
    float* hout = out + (size_t)t * BSZ * HH;
    {
        if (t > 0) {
            #pragma unroll
            for (int q = 0; q < 8; ++q) {
                const int base = (q * 64 + erow) * 33;
                gi += ps[base + ehl];
                gf += ps[base + 8 + ehl];
                gg += ps[base + 16 + ehl];
                go += ps[base + 24 + ehl];
            }
        }
        const float iv = __saturatef(gi + 0.5f);
        const float fv = __saturatef(gf + 0.5f);
        const float gv = fminf(fmaxf(gg, -1.0f), 1.0f);
        const float ov = __saturatef(go + 0.5f);
        const float cnew = fv * cold + iv * gv;
        const float hnew = ov * fminf(fmaxf(cnew, -1.0f), 1.0f);
        g_c[erow * HH + encol] = cnew;
        hout[(size_t)erow * HH + encol] = hnew;
        hs[ehl * 65 + erow] = hnew;        // bounce for transposed write
    }
    __syncthreads();

    // Coalesced transposed h write for next step: g_hT[hcol][row].
    {
        const int q   = tid;
        const int hl  = q >> 6;            // 0..7
        const int row = q & 63;
        g_hT[(size_t)(cta * 8 + hl) * BSZ + row] = hs[hl * 65 + row];
    }
}

// ---------------------------------------------------------------------------
extern "C" void kernel_launch(void* const* d_in, const int* in_sizes, int n_in,
                              void* d_out, int out_size) {
    const float* x  = (const float*)d_in[0];   // [T, B, D]
    const float* Wx = (const float*)d_in[1];   // [D, 4H]
    const float* Wh = (const float*)d_in[2];   // [H, 4H]
    const float* b  = (const float*)d_in[3];   // [4H]
    float* out = (float*)d_out;                // [T, B, H]

    cudaFuncSetAttribute(lstm_step9, cudaFuncAttributeMaxDynamicSharedMemorySize,
                         SM9_TOTAL);

    // Phase 0: one-time gather of Wh into per-CTA contiguous slices.
    dim3 gw(128, 8);
    wgather<<<gw, 256>>>(Wh);

    // Phase 1: precompute G = X @ Wx + b for all timesteps (proven kernel).
    dim3 g1(NG / 128, (TT * BSZ) / 128);       // (32, 64)
    gemm_pre<<<g1, 256>>>(x, Wx, b);

    // Phase 2: 128 sequential fused recurrent steps.
    for (int t = 0; t < TT; ++t) {
        lstm_step9<<<128, STEP_THREADS, SM9_TOTAL>>>(out, t);
    }
    (void)in_sizes; (void)n_in; (void)out_size;
}

// round 17
// speedup vs baseline: 1.2338x; 1.2338x over previous
#include <cuda_runtime.h>

#define TT  128
#define BSZ 64
#define DD  1024
#define HH  1024
#define NG  4096   // 4*H

typedef unsigned int u32;
typedef unsigned long long u64;

// Scratch (device globals: no allocation allowed in kernel_launch)
__device__ __align__(16) float g_G[(size_t)TT * BSZ * NG];     // x@Wx + b
__device__ __align__(16) float g_c[BSZ * HH];                  // cell state
__device__ __align__(16) float g_WhP[(size_t)128 * HH * 32];   // gathered Wh slices
__device__ __align__(16) float g_hT[HH * BSZ];                 // h transposed [hcol][row]

__device__ __forceinline__ u64 fma2(u64 a, u64 b, u64 c) {
    u64 d;
    asm("fma.rn.f32x2 %0, %1, %2, %3;" : "=l"(d) : "l"(a), "l"(b), "l"(c));
    return d;
}
__device__ __forceinline__ u64 pack2(float lo, float hi) {
    u64 d;
    asm("mov.b64 %0, {%1, %2};" : "=l"(d) : "f"(lo), "f"(hi));
    return d;
}
__device__ __forceinline__ void unpack2(u64 v, float& lo, float& hi) {
    asm("mov.b64 {%0, %1}, %2;" : "=f"(lo), "=f"(hi) : "l"(v));
}

// ---------------------------------------------------------------------------
// Phase 0: gather Wh into per-CTA contiguous slices (proven, rounds 11/12).
// ---------------------------------------------------------------------------
__global__ __launch_bounds__(256) void wgather(const float* __restrict__ Wh) {
    const int c  = blockIdx.x;
    const int kb = blockIdx.y;
    const int t  = threadIdx.x;
    float* dst = g_WhP + (size_t)c * (HH * 32);
    #pragma unroll
    for (int i = 0; i < 4; ++i) {
        const int q    = kb * 1024 + i * 256 + t;
        const int base = q * 4;
        const int k    = base >> 5;
        const int j    = base & 31;
        const int gcol = (j >> 3) * HH + c * 8 + (j & 7);
        float4 v = *(const float4*)(Wh + (size_t)k * NG + gcol);
        *(float4*)(dst + base) = v;
    }
}

// ---------------------------------------------------------------------------
// Phase 1: G[8192,4096] = X @ Wx + b — round-1 FFMA kernel VERBATIM with
// PLAIN stores (A/B-tested: __stcs here cost ~120us; plain is ~990us ≈ f32x2
// peak, 69 TF/s).
// ---------------------------------------------------------------------------
__global__ __launch_bounds__(256) void gemm_pre(const float* __restrict__ X,
                                                const float* __restrict__ Wx,
                                                const float* __restrict__ bias) {
    const int N = NG, K = DD;
    __shared__ float As[2][8][128];
    __shared__ float Bs[2][8][128];

    const int tid  = threadIdx.x;
    const int bx   = blockIdx.x;
    const int by   = blockIdx.y;
    const int aRow = tid >> 1;
    const int aK4  = (tid & 1) << 2;
    const int bK   = tid >> 5;
    const int bN4  = (tid & 31) << 2;
    const int tx   = tid & 15;
    const int ty   = tid >> 4;

    const float* Ap = X  + (size_t)(by * 128) * K;
    const float* Bp = Wx + (size_t)(bx * 128);

    float4 aR = *(const float4*)(Ap + (size_t)aRow * K + aK4);
    float4 bR = *(const float4*)(Bp + (size_t)bK * N + bN4);
    As[0][aK4 + 0][aRow] = aR.x;
    As[0][aK4 + 1][aRow] = aR.y;
    As[0][aK4 + 2][aRow] = aR.z;
    As[0][aK4 + 3][aRow] = aR.w;
    *(float4*)&Bs[0][bK][bN4] = bR;
    __syncthreads();

    u64 acc[4][8];
    #pragma unroll
    for (int i = 0; i < 4; ++i)
        #pragma unroll
        for (int j = 0; j < 8; ++j) acc[i][j] = 0ull;

    const int nT = K / 8;
    for (int tk = 0; tk < nT; ++tk) {
        const int cur = tk & 1;
        if (tk + 1 < nT) {
            const int k0 = (tk + 1) * 8;
            aR = *(const float4*)(Ap + (size_t)aRow * K + k0 + aK4);
            bR = *(const float4*)(Bp + (size_t)(k0 + bK) * N + bN4);
        }
        #pragma unroll
        for (int kk = 0; kk < 8; ++kk) {
            const ulonglong2 a01 = *(const ulonglong2*)&As[cur][kk][ty * 8];
            const ulonglong2 a23 = *(const ulonglong2*)&As[cur][kk][ty * 8 + 4];
            u64 ap[4];
            ap[0] = a01.x; ap[1] = a01.y; ap[2] = a23.x; ap[3] = a23.y;
            float br[8];
            *(float4*)&br[0] = *(const float4*)&Bs[cur][kk][tx * 8];
            *(float4*)&br[4] = *(const float4*)&Bs[cur][kk][tx * 8 + 4];
            #pragma unroll
            for (int j = 0; j < 8; ++j) {
                const u64 bb = pack2(br[j], br[j]);
                #pragma unroll
                for (int i = 0; i < 4; ++i)
                    acc[i][j] = fma2(ap[i], bb, acc[i][j]);
            }
        }
        if (tk + 1 < nT) {
            const int nxt = cur ^ 1;
            As[nxt][aK4 + 0][aRow] = aR.x;
            As[nxt][aK4 + 1][aRow] = aR.y;
            As[nxt][aK4 + 2][aRow] = aR.z;
            As[nxt][aK4 + 3][aRow] = aR.w;
            *(float4*)&Bs[nxt][bK][bN4] = bR;
            __syncthreads();
        }
    }

    float* Gp = g_G + (size_t)(by * 128) * N + (size_t)(bx * 128);
    #pragma unroll
    for (int i = 0; i < 4; ++i) {
        #pragma unroll
        for (int j = 0; j < 8; ++j) {
            float lo, hi;
            unpack2(acc[i][j], lo, hi);
            const int col = tx * 8 + j;
            const float bv = bias[bx * 128 + col];
            Gp[(size_t)(ty * 8 + 2 * i)     * N + col] = lo + bv;
            Gp[(size_t)(ty * 8 + 2 * i + 1) * N + col] = hi + bv;
        }
    }
}

// ---------------------------------------------------------------------------
// Phase 2: round-15 step kernel VERBATIM (best measured: 19.84us).
// Warp-autonomous, 16 warps, __syncwarp only; tail (G/c) prefetched at entry
// with __ldcs; round-12 inner loop (A/B-proven optimal vs all pack2-free
// variants tried in rounds 13/14/16).
// smem: ps [8][64][33] f32 @0         (67584 B)
//       hT [16 warps][2][16][32] f32 @67584  (65536 B)
//       wS [16 warps][2][16][32] f32 @133120 (65536 B)
//       hs [8][65] f32 @198656        (2080 B)   total 200736 B
// ---------------------------------------------------------------------------
#define STEP_THREADS 512
#define PS5_OFF 0
#define HT5_OFF 67584
#define WS5_OFF 133120
#define HS5_OFF 198656
#define SM5_TOTAL 200736

__global__ __launch_bounds__(STEP_THREADS) void lstm_step8(
    float* __restrict__ out, int t)
{
    extern __shared__ char sm[];
    float* ps = (float*)(sm + PS5_OFF);
    float* hs = (float*)(sm + HS5_OFF);

    const int tid  = threadIdx.x;
    const int cta  = blockIdx.x;         // 0..127
    const int w    = tid >> 5;           // warp 0..15
    const int kg   = w >> 1;             // k-group 0..7
    const int half = w & 1;              // row half
    const int lane = tid & 31;
    const int rg   = lane & 7;
    const int cg   = lane >> 3;
    const int r0   = rg * 4;             // local row (within 32-row half)
    const int j0   = cg * 8;

    // ---- Epilogue prefetch (independent of mainloop; latency hidden) ----
    const int erow  = tid >> 3;
    const int ehl   = tid & 7;
    const int encol = cta * 8 + ehl;
    const float* Grow = g_G + (size_t)t * BSZ * NG + (size_t)erow * NG;
    float gi = __ldcs(Grow + encol);
    float gf = __ldcs(Grow + HH + encol);
    float gg = __ldcs(Grow + 2 * HH + encol);
    float go = __ldcs(Grow + 3 * HH + encol);
    float cold = 0.0f;
    if (t > 0) cold = g_c[erow * HH + encol];

    u64 acc[2][8];
    #pragma unroll
    for (int p = 0; p < 2; ++p)
        #pragma unroll
        for (int j = 0; j < 8; ++j) acc[p][j] = 0ull;

    if (t > 0) {
        const int kbase = kg * 128;
        float* hTw = (float*)(sm + HT5_OFF) + w * 1024;  // 2 bufs x 512 f32
        float* wSw = (float*)(sm + WS5_OFF) + w * 1024;  // 2 bufs x 512 f32

        const float* wSrc = g_WhP + (size_t)cta * (HH * 32) + (size_t)kbase * 32;

        float4 hv[4], wv[4];
#define P8L(ck) do {                                                         \
    _Pragma("unroll")                                                        \
    for (int i = 0; i < 4; ++i) {                                            \
        const int f  = lane + 32 * i;                                        \
        const int kk = f >> 3, q = f & 7;                                    \
        hv[i] = *(const float4*)(g_hT + (size_t)(kbase + (ck) * 16 + kk) * 64 \
                                 + half * 32 + q * 4);                       \
        wv[i] = *(const float4*)(wSrc + (ck) * 512 + f * 4);                 \
    }                                                                        \
} while (0)
#define P8S(buf) do {                                                        \
    float* hd_ = hTw + (buf) * 512;                                          \
    float* wd_ = wSw + (buf) * 512;                                          \
    _Pragma("unroll")                                                        \
    for (int i = 0; i < 4; ++i) {                                            \
        const int f = lane + 32 * i;                                         \
        *(float4*)(hd_ + f * 4) = hv[i];                                     \
        *(float4*)(wd_ + f * 4) = wv[i];                                     \
    }                                                                        \
} while (0)

        P8L(0);
        P8S(0);
        __syncwarp();

        for (int c = 0; c < 8; ++c) {
            const int buf = c & 1;
            if (c + 1 < 8) P8L(c + 1);

            const float* hb = hTw + buf * 512;
            const float* wb = wSw + buf * 512;
            #pragma unroll
            for (int kk = 0; kk < 16; ++kk) {
                const ulonglong2 hA = *(const ulonglong2*)(hb + kk * 32 + r0);
                const float4 wq0 = *(const float4*)(wb + kk * 32 + j0);
                const float4 wq1 = *(const float4*)(wb + kk * 32 + j0 + 4);
                float wf[8];
                wf[0] = wq0.x; wf[1] = wq0.y; wf[2] = wq0.z; wf[3] = wq0.w;
                wf[4] = wq1.x; wf[5] = wq1.y; wf[6] = wq1.z; wf[7] = wq1.w;
                #pragma unroll
                for (int j = 0; j < 8; ++j) {
                    const u64 wd = pack2(wf[j], wf[j]);
                    acc[0][j] = fma2(hA.x, wd, acc[0][j]);
                    acc[1][j] = fma2(hA.y, wd, acc[1][j]);
                }
            }
            if (c + 1 < 8) {
                P8S(buf ^ 1);
                __syncwarp();
            }
        }

        // stash partials: ps[kg][half*32 + local_row][col], pad 33
        #pragma unroll
        for (int p = 0; p < 2; ++p) {
            #pragma unroll
            for (int j = 0; j < 8; ++j) {
                float lo, hi;
                unpack2(acc[p][j], lo, hi);
                const int rb = kg * 64 + half * 32 + r0 + 2 * p;
                ps[rb * 33 + j0 + j]       = lo;
                ps[(rb + 1) * 33 + j0 + j] = hi;
            }
        }
    }
    __syncthreads();

    // Epilogue: 512 threads -> 512 outputs; G/c already in registers.
    float* hout = out + (size_t)t * BSZ * HH;
    {
        if (t > 0) {
            #pragma unroll
            for (int q = 0; q < 8; ++q) {
                const int base = (q * 64 + erow) * 33;
                gi += ps[base + ehl];
                gf += ps[base + 8 + ehl];
                gg += ps[base + 16 + ehl];
                go += ps[base + 24 + ehl];
            }
        }
        const float iv = __saturatef(gi + 0.5f);
        const float fv = __saturatef(gf + 0.5f);
        const float gv = fminf(fmaxf(gg, -1.0f), 1.0f);
        const float ov = __saturatef(go + 0.5f);
        const float cnew = fv * cold + iv * gv;
        const float hnew = ov * fminf(fmaxf(cnew, -1.0f), 1.0f);
        g_c[erow * HH + encol] = cnew;
        hout[(size_t)erow * HH + encol] = hnew;
        hs[ehl * 65 + erow] = hnew;        // bounce for transposed write
    }
    __syncthreads();

    // Coalesced transposed h write for next step: g_hT[hcol][row].
    {
        const int q   = tid;
        const int hl  = q >> 6;            // 0..7
        const int row = q & 63;
        g_hT[(size_t)(cta * 8 + hl) * BSZ + row] = hs[hl * 65 + row];
    }
}

// ---------------------------------------------------------------------------
extern "C" void kernel_launch(void* const* d_in, const int* in_sizes, int n_in,
                              void* d_out, int out_size) {
    const float* x  = (const float*)d_in[0];   // [T, B, D]
    const float* Wx = (const float*)d_in[1];   // [D, 4H]
    const float* Wh = (const float*)d_in[2];   // [H, 4H]
    const float* b  = (const float*)d_in[3];   // [4H]
    float* out = (float*)d_out;                // [T, B, H]

    cudaFuncSetAttribute(lstm_step8, cudaFuncAttributeMaxDynamicSharedMemorySize,
                         SM5_TOTAL);

    // Phase 0: one-time gather of Wh into per-CTA contiguous slices.
    dim3 gw(128, 8);
    wgather<<<gw, 256>>>(Wh);

    // Phase 1: precompute G = X @ Wx + b for all timesteps (proven kernel).
    dim3 g1(NG / 128, (TT * BSZ) / 128);       // (32, 64)
    gemm_pre<<<g1, 256>>>(x, Wx, b);

    // Phase 2: 128 sequential fused recurrent steps.
    for (int t = 0; t < TT; ++t) {
        lstm_step8<<<128, STEP_THREADS, SM5_TOTAL>>>(out, t);
    }
    (void)in_sizes; (void)n_in; (void)out_size;
}